// round 2
// baseline (speedup 1.0000x reference)
#include <cuda_runtime.h>

#define NN 131072
#define DD 64
#define KK 512
#define ITERS 5
#define NT 16          // centers per smem tile

// ---------------- scratch (device globals; no allocation allowed) ----------
__device__ float g_centers[KK * DD];
__device__ float g_c2[KK];
__device__ float g_sums[KK * DD];
__device__ float g_counts[KK];
__device__ int   g_assign[NN];

// ---------------- packed f32x2 helpers -------------------------------------
__device__ __forceinline__ unsigned long long fma2(unsigned long long a,
                                                   unsigned long long b,
                                                   unsigned long long c) {
    unsigned long long d;
    asm("fma.rn.f32x2 %0, %1, %2, %3;" : "=l"(d) : "l"(a), "l"(b), "l"(c));
    return d;
}
__device__ __forceinline__ float lo32(unsigned long long v) {
    return __uint_as_float((unsigned)v);
}
__device__ __forceinline__ float hi32(unsigned long long v) {
    return __uint_as_float((unsigned)(v >> 32));
}

// ---------------- prep: zero sums/counts, c2 of initial centers ------------
__global__ void prep_kernel(const float* __restrict__ centers0) {
    int k = blockIdx.x;
    int d = threadIdx.x;
    float v = centers0[k * DD + d];
    g_sums[k * DD + d] = 0.0f;
    if (d == 0) g_counts[k] = 0.0f;

    float s = __fmul_rn(v, v);
    #pragma unroll
    for (int o = 16; o > 0; o >>= 1) s += __shfl_down_sync(0xffffffffu, s, o);
    __shared__ float sh[2];
    if ((d & 31) == 0) sh[d >> 5] = s;
    __syncthreads();
    if (d == 0) g_c2[k] = __fadd_rn(sh[0], sh[1]);
}

// ---------------- assign + accumulate (fused) ------------------------------
// 128 threads/block, each thread owns 2 rows of X (full D=64 in registers as
// 32 packed f32x2 each). Centers staged 16 at a time in smem; broadcast LDS.
__global__ __launch_bounds__(128) void assign_kernel(
    const float* __restrict__ X,
    const float* __restrict__ centers0,
    int iter)
{
    const float* __restrict__ C = (iter == 0) ? centers0 : g_centers;

    __shared__ __align__(16) float sc[NT][DD];
    __shared__ float sc2[NT];

    const int tid  = threadIdx.x;
    const int row0 = blockIdx.x * 256 + tid;
    const int row1 = row0 + 128;

    unsigned long long x0[32], x1[32];
    {
        const ulonglong2* R0 = (const ulonglong2*)(X + (size_t)row0 * DD);
        const ulonglong2* R1 = (const ulonglong2*)(X + (size_t)row1 * DD);
        #pragma unroll
        for (int q = 0; q < 16; q++) {
            ulonglong2 a = R0[q];
            ulonglong2 b = R1[q];
            x0[2 * q] = a.x; x0[2 * q + 1] = a.y;
            x1[2 * q] = b.x; x1[2 * q + 1] = b.y;
        }
    }
    // x^2 per row (packed)
    float x2_0, x2_1;
    {
        unsigned long long a0 = 0ULL, b0 = 0ULL, a1 = 0ULL, b1 = 0ULL;
        #pragma unroll
        for (int p = 0; p < 32; p += 2) {
            a0 = fma2(x0[p],     x0[p],     a0);
            b0 = fma2(x0[p + 1], x0[p + 1], b0);
            a1 = fma2(x1[p],     x1[p],     a1);
            b1 = fma2(x1[p + 1], x1[p + 1], b1);
        }
        x2_0 = __fadd_rn(__fadd_rn(lo32(a0), hi32(a0)),
                         __fadd_rn(lo32(b0), hi32(b0)));
        x2_1 = __fadd_rn(__fadd_rn(lo32(a1), hi32(a1)),
                         __fadd_rn(lo32(b1), hi32(b1)));
    }

    float best0 = 3.4e38f, best1 = 3.4e38f;
    int   bi0 = 0, bi1 = 0;

    for (int t = 0; t < KK / NT; t++) {
        // cooperative stage: 16 centers * 64 floats = 256 float4
        const float4* Cp = (const float4*)(C + (size_t)t * NT * DD);
        float4* S4 = (float4*)&sc[0][0];
        S4[tid]       = Cp[tid];
        S4[tid + 128] = Cp[tid + 128];
        if (tid < NT) sc2[tid] = g_c2[t * NT + tid];
        __syncthreads();

        #pragma unroll 1
        for (int j = 0; j < NT; j++) {
            const unsigned long long* c = (const unsigned long long*)&sc[j][0];
            unsigned long long A0 = 0ULL, B0 = 0ULL, A1 = 0ULL, B1 = 0ULL;
            #pragma unroll
            for (int p = 0; p < 32; p += 2) {
                unsigned long long c0 = c[p], c1 = c[p + 1];
                A0 = fma2(x0[p],     c0, A0);
                A1 = fma2(x1[p],     c0, A1);
                B0 = fma2(x0[p + 1], c1, B0);
                B1 = fma2(x1[p + 1], c1, B1);
            }
            float dot0 = __fadd_rn(__fadd_rn(lo32(A0), hi32(A0)),
                                   __fadd_rn(lo32(B0), hi32(B0)));
            float dot1 = __fadd_rn(__fadd_rn(lo32(A1), hi32(A1)),
                                   __fadd_rn(lo32(B1), hi32(B1)));
            float cc = sc2[j];
            float d20 = __fsub_rn(__fadd_rn(x2_0, cc), __fmul_rn(2.0f, dot0));
            float d21 = __fsub_rn(__fadd_rn(x2_1, cc), __fmul_rn(2.0f, dot1));
            int kg = t * NT + j;
            if (d20 < best0) { best0 = d20; bi0 = kg; }
            if (d21 < best1) { best1 = d21; bi1 = kg; }
        }
        __syncthreads();
    }

    g_assign[row0] = bi0;
    g_assign[row1] = bi1;
    atomicAdd(&g_counts[bi0], 1.0f);
    atomicAdd(&g_counts[bi1], 1.0f);
    float* s0 = &g_sums[(size_t)bi0 * DD];
    float* s1 = &g_sums[(size_t)bi1 * DD];
    #pragma unroll
    for (int p = 0; p < 32; p++) {
        atomicAdd(&s0[2 * p],     lo32(x0[p]));
        atomicAdd(&s0[2 * p + 1], hi32(x0[p]));
        atomicAdd(&s1[2 * p],     lo32(x1[p]));
        atomicAdd(&s1[2 * p + 1], hi32(x1[p]));
    }
}

// ---------------- centers update (+ c2, + reset sums/counts) ---------------
__global__ void update_kernel(const float* __restrict__ X,
                              const int* __restrict__ repl,
                              int iter)
{
    int k = blockIdx.x;
    int d = threadIdx.x;
    float cnt = g_counts[k];
    float s   = g_sums[k * DD + d];
    float v   = __fdiv_rn(s, fmaxf(cnt, 1.0f));
    if (v == 0.0f) {
        int r = repl[iter * KK + k];
        v = X[(size_t)r * DD + d];
    }
    g_centers[k * DD + d] = v;
    g_sums[k * DD + d] = 0.0f;
    if (d == 0) g_counts[k] = 0.0f;

    float sq = __fmul_rn(v, v);
    #pragma unroll
    for (int o = 16; o > 0; o >>= 1) sq += __shfl_down_sync(0xffffffffu, sq, o);
    __shared__ float sh[2];
    if ((d & 31) == 0) sh[d >> 5] = sq;
    __syncthreads();
    if (d == 0) g_c2[k] = __fadd_rn(sh[0], sh[1]);
}

// ---------------- output: [assignments as float | centers] -----------------
__global__ void out_kernel(float* __restrict__ out) {
    int i = blockIdx.x * blockDim.x + threadIdx.x;
    if (i < NN) {
        out[i] = (float)g_assign[i];
    } else if (i < NN + KK * DD) {
        out[i] = g_centers[i - NN];
    }
}

// ---------------- launch ----------------------------------------------------
extern "C" void kernel_launch(void* const* d_in, const int* in_sizes, int n_in,
                              void* d_out, int out_size)
{
    const float* X    = nullptr;
    const float* C0   = nullptr;
    const int*   repl = nullptr;
    for (int i = 0; i < n_in; i++) {
        if (in_sizes[i] == NN * DD)       X    = (const float*)d_in[i];
        else if (in_sizes[i] == KK * DD)  C0   = (const float*)d_in[i];
        else if (in_sizes[i] == ITERS*KK) repl = (const int*)d_in[i];
    }
    float* out = (float*)d_out;

    prep_kernel<<<KK, DD>>>(C0);
    for (int i = 0; i < ITERS; i++) {
        assign_kernel<<<NN / 256, 128>>>(X, C0, i);
        update_kernel<<<KK, DD>>>(X, repl, i);
    }
    int total = NN + KK * DD;
    out_kernel<<<(total + 255) / 256, 256>>>(out);
}

// round 3
// speedup vs baseline: 1.2604x; 1.2604x over previous
#include <cuda_runtime.h>

#define NN 131072
#define DD 64
#define KK 512
#define ITERS 5
#define NT 32            // centers per smem tile
#define NTILES (KK / NT)

// ---------------- scratch (device globals; no allocation allowed) ----------
__device__ __align__(256) float g_centers[KK * DD];
__device__ float g_c2[KK];
__device__ __align__(256) float g_sums[KK * DD];
__device__ float g_counts[KK];
__device__ int   g_assign[NN];

// ---------------- packed f32x2 helpers -------------------------------------
__device__ __forceinline__ unsigned long long fma2(unsigned long long a,
                                                   unsigned long long b,
                                                   unsigned long long c) {
    unsigned long long d;
    asm("fma.rn.f32x2 %0, %1, %2, %3;" : "=l"(d) : "l"(a), "l"(b), "l"(c));
    return d;
}
__device__ __forceinline__ float lo32(unsigned long long v) {
    return __uint_as_float((unsigned)v);
}
__device__ __forceinline__ float hi32(unsigned long long v) {
    return __uint_as_float((unsigned)(v >> 32));
}

// ---------------- cp.async + vector red helpers ----------------------------
__device__ __forceinline__ void cp_async16(unsigned s, const void* g) {
    asm volatile("cp.async.cg.shared.global [%0], [%1], 16;\n" :: "r"(s), "l"(g));
}
__device__ __forceinline__ void cp_commit() {
    asm volatile("cp.async.commit_group;\n");
}
__device__ __forceinline__ void cp_wait1() {
    asm volatile("cp.async.wait_group 1;\n");
}
__device__ __forceinline__ void cp_wait0() {
    asm volatile("cp.async.wait_group 0;\n");
}
__device__ __forceinline__ void red_add_v4(float* p, float a, float b, float c, float d) {
    asm volatile("red.global.add.v4.f32 [%0], {%1, %2, %3, %4};\n"
                 :: "l"(p), "f"(a), "f"(b), "f"(c), "f"(d) : "memory");
}

// ---------------- prep: zero sums/counts, c2 of initial centers ------------
__global__ void prep_kernel(const float* __restrict__ centers0) {
    int k = blockIdx.x;
    int d = threadIdx.x;
    float v = centers0[k * DD + d];
    g_sums[k * DD + d] = 0.0f;
    if (d == 0) g_counts[k] = 0.0f;

    float s = __fmul_rn(v, v);
    #pragma unroll
    for (int o = 16; o > 0; o >>= 1) s += __shfl_down_sync(0xffffffffu, s, o);
    __shared__ float sh[2];
    if ((d & 31) == 0) sh[d >> 5] = s;
    __syncthreads();
    if (d == 0) g_c2[k] = __fadd_rn(sh[0], sh[1]);
}

// ---------------- assign + accumulate (fused) ------------------------------
// 128 threads/block, each thread owns 2 rows of X (full D=64 in registers as
// 32 packed f32x2 each). Centers staged 32 at a time via cp.async double
// buffering; LDS.128 center reads; dot-product summation order identical to
// the validated round-1 kernel.
__global__ __launch_bounds__(128, 3) void assign_kernel(
    const float* __restrict__ X,
    const float* __restrict__ centers0,
    int iter)
{
    const float* __restrict__ C = (iter == 0) ? centers0 : g_centers;

    __shared__ __align__(16) float sbuf[2][NT * DD];   // 2 x 8KB
    __shared__ float sc2[KK];

    const int tid  = threadIdx.x;
    const int row0 = blockIdx.x * 256 + tid;
    const int row1 = row0 + 128;

    // stage all c2 once (consumed only after the first barrier)
    #pragma unroll
    for (int i = 0; i < KK / 128; i++) sc2[tid + i * 128] = g_c2[tid + i * 128];

    unsigned sb[2];
    sb[0] = (unsigned)__cvta_generic_to_shared(&sbuf[0][0]);
    sb[1] = (unsigned)__cvta_generic_to_shared(&sbuf[1][0]);

    // x rows resident in registers (packed f32x2)
    unsigned long long x0[32], x1[32];
    {
        const ulonglong2* R0 = (const ulonglong2*)(X + (size_t)row0 * DD);
        const ulonglong2* R1 = (const ulonglong2*)(X + (size_t)row1 * DD);
        #pragma unroll
        for (int q = 0; q < 16; q++) {
            ulonglong2 a = R0[q];
            ulonglong2 b = R1[q];
            x0[2 * q] = a.x; x0[2 * q + 1] = a.y;
            x1[2 * q] = b.x; x1[2 * q + 1] = b.y;
        }
    }
    // x^2 per row (packed) — identical order to round 1
    float x2_0, x2_1;
    {
        unsigned long long a0 = 0ULL, b0 = 0ULL, a1 = 0ULL, b1 = 0ULL;
        #pragma unroll
        for (int p = 0; p < 32; p += 2) {
            a0 = fma2(x0[p],     x0[p],     a0);
            b0 = fma2(x0[p + 1], x0[p + 1], b0);
            a1 = fma2(x1[p],     x1[p],     a1);
            b1 = fma2(x1[p + 1], x1[p + 1], b1);
        }
        x2_0 = __fadd_rn(__fadd_rn(lo32(a0), hi32(a0)),
                         __fadd_rn(lo32(b0), hi32(b0)));
        x2_1 = __fadd_rn(__fadd_rn(lo32(a1), hi32(a1)),
                         __fadd_rn(lo32(b1), hi32(b1)));
    }

    // prologue: stage tiles 0 and 1
    {
        const char* src0 = (const char*)(C);
        const char* src1 = (const char*)(C + (size_t)NT * DD);
        #pragma unroll
        for (int k = 0; k < 4; k++)
            cp_async16(sb[0] + tid * 16 + k * 2048, src0 + tid * 16 + k * 2048);
        cp_commit();
        #pragma unroll
        for (int k = 0; k < 4; k++)
            cp_async16(sb[1] + tid * 16 + k * 2048, src1 + tid * 16 + k * 2048);
        cp_commit();
    }

    float best0 = 3.4e38f, best1 = 3.4e38f;
    int   bi0 = 0, bi1 = 0;

    for (int t = 0; t < NTILES; t++) {
        if (t == NTILES - 1) cp_wait0(); else cp_wait1();
        __syncthreads();
        const int buf = t & 1;

        #pragma unroll 1
        for (int j = 0; j < NT; j++) {
            const ulonglong2* c = (const ulonglong2*)&sbuf[buf][j * DD];
            unsigned long long A0 = 0ULL, B0 = 0ULL, A1 = 0ULL, B1 = 0ULL;
            #pragma unroll
            for (int q = 0; q < 16; q++) {
                ulonglong2 cc2 = c[q];                 // c[2q], c[2q+1]
                A0 = fma2(x0[2 * q],     cc2.x, A0);
                A1 = fma2(x1[2 * q],     cc2.x, A1);
                B0 = fma2(x0[2 * q + 1], cc2.y, B0);
                B1 = fma2(x1[2 * q + 1], cc2.y, B1);
            }
            float dot0 = __fadd_rn(__fadd_rn(lo32(A0), hi32(A0)),
                                   __fadd_rn(lo32(B0), hi32(B0)));
            float dot1 = __fadd_rn(__fadd_rn(lo32(A1), hi32(A1)),
                                   __fadd_rn(lo32(B1), hi32(B1)));
            float cc = sc2[t * NT + j];
            float d20 = __fsub_rn(__fadd_rn(x2_0, cc), __fmul_rn(2.0f, dot0));
            float d21 = __fsub_rn(__fadd_rn(x2_1, cc), __fmul_rn(2.0f, dot1));
            int kg = t * NT + j;
            if (d20 < best0) { best0 = d20; bi0 = kg; }
            if (d21 < best1) { best1 = d21; bi1 = kg; }
        }
        __syncthreads();

        if (t + 2 < NTILES) {
            const char* src = (const char*)(C + (size_t)(t + 2) * NT * DD);
            #pragma unroll
            for (int k = 0; k < 4; k++)
                cp_async16(sb[buf] + tid * 16 + k * 2048, src + tid * 16 + k * 2048);
            cp_commit();
        }
    }

    g_assign[row0] = bi0;
    g_assign[row1] = bi1;
    atomicAdd(&g_counts[bi0], 1.0f);
    atomicAdd(&g_counts[bi1], 1.0f);
    float* s0 = &g_sums[(size_t)bi0 * DD];
    float* s1 = &g_sums[(size_t)bi1 * DD];
    #pragma unroll
    for (int p = 0; p < 32; p += 2) {
        red_add_v4(&s0[2 * p], lo32(x0[p]),     hi32(x0[p]),
                               lo32(x0[p + 1]), hi32(x0[p + 1]));
        red_add_v4(&s1[2 * p], lo32(x1[p]),     hi32(x1[p]),
                               lo32(x1[p + 1]), hi32(x1[p + 1]));
    }
}

// ---------------- centers update (+ c2, + reset sums/counts) ---------------
__global__ void update_kernel(const float* __restrict__ X,
                              const int* __restrict__ repl,
                              int iter)
{
    int k = blockIdx.x;
    int d = threadIdx.x;
    float cnt = g_counts[k];
    float s   = g_sums[k * DD + d];
    float v   = __fdiv_rn(s, fmaxf(cnt, 1.0f));
    if (v == 0.0f) {
        int r = repl[iter * KK + k];
        v = X[(size_t)r * DD + d];
    }
    g_centers[k * DD + d] = v;
    g_sums[k * DD + d] = 0.0f;
    if (d == 0) g_counts[k] = 0.0f;

    float sq = __fmul_rn(v, v);
    #pragma unroll
    for (int o = 16; o > 0; o >>= 1) sq += __shfl_down_sync(0xffffffffu, sq, o);
    __shared__ float sh[2];
    if ((d & 31) == 0) sh[d >> 5] = sq;
    __syncthreads();
    if (d == 0) g_c2[k] = __fadd_rn(sh[0], sh[1]);
}

// ---------------- output: [assignments as float | centers] -----------------
__global__ void out_kernel(float* __restrict__ out) {
    int i = blockIdx.x * blockDim.x + threadIdx.x;
    if (i < NN) {
        out[i] = (float)g_assign[i];
    } else if (i < NN + KK * DD) {
        out[i] = g_centers[i - NN];
    }
}

// ---------------- launch ----------------------------------------------------
extern "C" void kernel_launch(void* const* d_in, const int* in_sizes, int n_in,
                              void* d_out, int out_size)
{
    const float* X    = nullptr;
    const float* C0   = nullptr;
    const int*   repl = nullptr;
    for (int i = 0; i < n_in; i++) {
        if (in_sizes[i] == NN * DD)       X    = (const float*)d_in[i];
        else if (in_sizes[i] == KK * DD)  C0   = (const float*)d_in[i];
        else if (in_sizes[i] == ITERS*KK) repl = (const int*)d_in[i];
    }
    float* out = (float*)d_out;

    prep_kernel<<<KK, DD>>>(C0);
    for (int i = 0; i < ITERS; i++) {
        assign_kernel<<<NN / 256, 128>>>(X, C0, i);
        update_kernel<<<KK, DD>>>(X, repl, i);
    }
    int total = NN + KK * DD;
    out_kernel<<<(total + 255) / 256, 256>>>(out);
}